// round 7
// baseline (speedup 1.0000x reference)
#include <cuda_runtime.h>
#include <cstdint>

// ---------------------------------------------------------------------------
// SSD post-processing:
//   inputs:  loc [32,8732,4] f32, conf [32,8732,21] f32, priors [8732,4] f32
//   output:  [32,21,200,5] f32  rows = [score, x1, y1, x2, y2]
// Pipelined: 4 chunks of 8 images; A-chunks chained, B-chunk c follows A-chunk c.
// ---------------------------------------------------------------------------

#define BATCH 32
#define NPRI  8732
#define NPRI4 2183          /* 8732 / 4 exactly */
#define NCLS  21
#define TOPK  200
#define CAP   256           /* candidate capacity (common path) */
#define NW    7             /* ceil(200/32) suppression words */
#define SUPW  8             /* padded row width */
#define NTB   384           /* threads per select block */
#define CITER 6             /* ceil(NPRI4 / NTB) */
#define NCHUNK 4
#define IMGS  8             /* images per chunk */
#define CONF_T 0.01f
#define NMS_T  0.45f
#define NMS_HI 0.45000180f  /* 0.45*(1+4e-6) */
#define NMS_LO 0.44999820f  /* 0.45*(1-4e-6) */
#define BASE16 0x3C00u      /* top16 of float bits; all valid keys above this */

// scratch (module-load allocated, not runtime alloc)
__device__ __align__(16) uint32_t g_keys[BATCH][NCLS-1][NPRI];
__device__ float4 g_boxes[BATCH][NPRI];

// ---------------------------------------------------------------------------
// Kernel A: softmax + decode for 8 images starting at b0. HBM-bound.
// ---------------------------------------------------------------------------
__global__ __launch_bounds__(256) void ssd_decode_softmax(
    const float* __restrict__ loc,
    const float* __restrict__ conf,
    const float* __restrict__ priors,
    int b0)
{
    int t = blockIdx.x * blockDim.x + threadIdx.x;
    if (t >= IMGS * NPRI) return;
    int b = b0 + t / NPRI;
    int p = t % NPRI;
    int gt = b * NPRI + p;

    const float* cf = conf + (size_t)gt * NCLS;
    float v[NCLS];
    float m = -1e30f;
#pragma unroll
    for (int c = 0; c < NCLS; c++) {
        float x = cf[c];
        x = fminf(fmaxf(x, -100.0f), 100.0f);
        v[c] = x;
        m = fmaxf(m, x);
    }
    float s = 0.0f;
#pragma unroll
    for (int c = 0; c < NCLS; c++) { v[c] = expf(v[c] - m); s += v[c]; }

    const float4 lp4 = ((const float4*)loc)[gt];
    const float4 pr4 = ((const float4*)priors)[p];
    float p0 = fmaxf(pr4.x, 1e-6f);
    float p1 = fmaxf(pr4.y, 1e-6f);
    float p2 = fmaxf(pr4.z, 1e-6f);
    float p3 = fmaxf(pr4.w, 1e-6f);
    float cx = p0 + lp4.x * 0.1f * p2;
    float cy = p1 + lp4.y * 0.1f * p3;
    float lw = fminf(fmaxf(lp4.z * 0.2f, -4.0f), 4.0f);
    float lh = fminf(fmaxf(lp4.w * 0.2f, -4.0f), 4.0f);
    float w = p2 * expf(lw);
    float h = p3 * expf(lh);
    float x1 = fminf(fmaxf(cx - w / 2.0f, 0.0f), 1.0f);
    float y1 = fminf(fmaxf(cy - h / 2.0f, 0.0f), 1.0f);
    float x2 = fminf(fmaxf(cx + w / 2.0f, 0.0f), 1.0f);
    float y2 = fminf(fmaxf(cy + h / 2.0f, 0.0f), 1.0f);
    g_boxes[b][p] = make_float4(x1, y1, x2, y2);

    bool bvalid = (x2 > x1 + 1e-6f) && (y2 > y1 + 1e-6f);
#pragma unroll
    for (int c = 1; c < NCLS; c++) {
        float sc = v[c] / s;
        uint32_t key = (bvalid && sc > CONF_T) ? __float_as_uint(sc) : 0u;
        g_keys[b][c - 1][p] = key;
    }
}

// ---------------------------------------------------------------------------
// Kernel B: per (image,class): replicated-histogram select, warp-aggregated
// collect, O(n^2) exact rank, split-row IoU masks, warp-parallel sweep.
// 168 blocks per chunk, 384 threads, 5 blocks/SM.
// ---------------------------------------------------------------------------
__global__ __launch_bounds__(NTB, 5) void ssd_select_nms(float* __restrict__ out,
                                                          int b0)
{
    __shared__ int hist[4][1024];      /* x4 replicated to cut ATOMS conflicts */
    __shared__ int part[256];
    __shared__ unsigned long long spk[CAP];
    __shared__ uint32_t sup[TOPK * SUPW];
    __shared__ float4 sbx[224];        /* padded: IoU reads j up to 223 (masked) */
    __shared__ float sar[224], ssc[TOPK];
    __shared__ uint32_t salive[8];
    __shared__ int sbase[8];
    __shared__ int sh[8];

    int bc = blockIdx.x;
    int b = b0 + bc / NCLS;
    int c = bc - (bc / NCLS) * NCLS;
    int tid = threadIdx.x;
    int lane = tid & 31;
    int* h0 = hist[0];
    float* orow = out + ((size_t)b * NCLS + c) * (TOPK * 5);

    if (c == 0) {
        for (int i = tid; i < TOPK * 5; i += NTB) orow[i] = 0.0f;
        return;
    }

    const uint32_t* gk = &g_keys[b][c - 1][0];
    const uint4* gk4 = (const uint4*)gk;

    // ---- P0: 16-bit digit histogram, 4 replicas (warp%4), then merge ----
    for (int i = tid; i < 4096; i += NTB) ((int*)hist)[i] = 0;
    __syncthreads();
    {
        int* hw = hist[(tid >> 5) & 3];
        for (int i = tid; i < NPRI4; i += NTB) {
            uint4 v = gk4[i];
            if (v.x) atomicAdd(&hw[(v.x >> 16) - BASE16], 1);
            if (v.y) atomicAdd(&hw[(v.y >> 16) - BASE16], 1);
            if (v.z) atomicAdd(&hw[(v.z >> 16) - BASE16], 1);
            if (v.w) atomicAdd(&hw[(v.w >> 16) - BASE16], 1);
        }
    }
    __syncthreads();
    if (tid < 256) {
        int4 a0 = ((const int4*)hist[0])[tid];
        int4 a1 = ((const int4*)hist[1])[tid];
        int4 a2 = ((const int4*)hist[2])[tid];
        int4 a3 = ((const int4*)hist[3])[tid];
        int4 s4 = make_int4(a0.x + a1.x + a2.x + a3.x,
                            a0.y + a1.y + a2.y + a3.y,
                            a0.z + a1.z + a2.z + a3.z,
                            a0.w + a1.w + a2.w + a3.w);
        ((int4*)hist[0])[tid] = s4;
        part[tid] = s4.x + s4.y + s4.z + s4.w;
    }
    __syncthreads();

    // ---- P1: warp 0 locates the 200th-largest digit via suffix scan ----
    if (tid < 32) {
        int s = 0;
#pragma unroll
        for (int q = 0; q < 8; q++) s += part[tid * 8 + q];
        int suf = s;
#pragma unroll
        for (int d = 1; d < 32; d <<= 1) {
            int o = __shfl_down_sync(0xFFFFFFFFu, suf, d);
            if (tid + d < 32) suf += o;
        }
        int sufN = __shfl_down_sync(0xFFFFFFFFu, suf, 1);
        if (tid == 31) sufN = 0;
        if (tid == 0) { sh[0] = -1; sh[6] = 0; }
        __syncwarp();
        if (suf >= TOPK && sufN < TOPK) { sh[0] = tid; sh[1] = sufN; }
        __syncwarp();
        if (tid == 0 && sh[0] >= 0) {
            int cum = sh[1];
            int d = sh[0] * 32 + 31;
            for (;; d--) { cum += h0[d]; if (cum >= TOPK) break; }
            sh[3] = d;                // digit of 200th value
            sh[4] = cum - h0[d];      // count with digit > d
            sh[5] = h0[d];
        }
    }
    __syncthreads();

    int ncand;
    bool rare = (sh[0] >= 0) && (sh[4] + sh[5] > CAP);
    if (!rare) {
        // ---- P2 common: collect keys >= digit floor, warp-aggregated push ----
        uint32_t thrK = (sh[0] < 0) ? (BASE16 << 16)
                                    : ((uint32_t)(BASE16 + (uint32_t)sh[3]) << 16);
        for (int i = tid; i < TOPK; i += NTB) ssc[i] = -1.0f;
#pragma unroll
        for (int it = 0; it < CITER; it++) {
            int i = tid + it * NTB;
            uint4 v = (i < NPRI4) ? gk4[i] : make_uint4(0u, 0u, 0u, 0u);
            int base4 = i * 4;
#pragma unroll
            for (int comp = 0; comp < 4; comp++) {
                uint32_t k = (comp == 0) ? v.x : (comp == 1) ? v.y : (comp == 2) ? v.z : v.w;
                int take = (k >= thrK);
                uint32_t bm = __ballot_sync(0xFFFFFFFFu, take);
                if (bm) {
                    int ldr = __ffs(bm) - 1;
                    int pos = 0;
                    if (lane == ldr) pos = atomicAdd(&sh[6], __popc(bm));
                    pos = __shfl_sync(0xFFFFFFFFu, pos, ldr);
                    if (take) {
                        int off = __popc(bm & ((1u << lane) - 1u));
                        spk[pos + off] = ((unsigned long long)k << 32)
                                       | (uint32_t)~(uint32_t)(base4 + comp);
                    }
                }
            }
        }
        __syncthreads();
        ncand = sh[6];
    } else {
        // ---- P2 rare (massive ties at cut digit): exact 32-bit refine ----
        for (int i = tid; i < TOPK; i += NTB) ssc[i] = -1.0f;
        uint32_t top16 = BASE16 + (uint32_t)sh[3];
        int cnt_gt = sh[4];
        if (tid < 256) h0[tid] = 0;
        __syncthreads();
        for (int i = tid; i < NPRI; i += NTB) {
            uint32_t k = gk[i];
            if ((k >> 16) == top16) atomicAdd(&h0[(k >> 8) & 0xFF], 1);
        }
        __syncthreads();
        if (tid == 0) {
            int cum = cnt_gt; int d = 255;
            for (;; d--) { cum += h0[d]; if (cum >= TOPK) break; }
            sh[3] = d; sh[4] = cum - h0[d];
        }
        __syncthreads();
        uint32_t pre24 = (top16 << 8) | (uint32_t)sh[3];
        cnt_gt = sh[4];
        if (tid < 256) h0[tid] = 0;
        __syncthreads();
        for (int i = tid; i < NPRI; i += NTB) {
            uint32_t k = gk[i];
            if ((k >> 8) == pre24) atomicAdd(&h0[k & 0xFF], 1);
        }
        __syncthreads();
        if (tid == 0) {
            int cum = cnt_gt; int d = 255;
            for (;; d--) { cum += h0[d]; if (cum >= TOPK) break; }
            sh[3] = d;
        }
        __syncthreads();
        uint32_t thr = (pre24 << 8) | (uint32_t)sh[3];
        for (int i = tid; i < NPRI; i += NTB) {
            uint32_t k = gk[i];
            if (k > thr) { int p = atomicAdd(&sh[6], 1); spk[p] = ((unsigned long long)k << 32) | (uint32_t)~(uint32_t)i; }
        }
        __syncthreads();
        if (tid == 0) {   // append ties in ascending index order
            int p = sh[6];
            for (int i = 0; i < NPRI && p < TOPK; i++)
                if (gk[i] == thr) { spk[p++] = ((unsigned long long)thr << 32) | (uint32_t)~(uint32_t)i; }
            sh[6] = p;
        }
        __syncthreads();
        ncand = sh[6];
    }

    // ---- P3: exact rank (key desc, index asc) + gather; idle threads zero out ----
    if (tid < ncand) {
        unsigned long long mypk = spk[tid];
        int rank = 0;
#pragma unroll 4
        for (int j = 0; j < ncand; j++) rank += (spk[j] > mypk) ? 1 : 0;
        if (rank < TOPK) {
            uint32_t kk = (uint32_t)(mypk >> 32);
            uint32_t idx = ~(uint32_t)mypk;
            float4 bx = g_boxes[b][idx];
            ssc[rank] = __uint_as_float(kk);
            sbx[rank] = bx;
            sar[rank] = (bx.z - bx.x) * (bx.w - bx.y);
        }
    } else if (tid >= 256) {
        for (int i = tid - 256; i < TOPK * 5; i += NTB - 256) orow[i] = 0.0f;
    }
    __syncthreads();
    int nval = ncand < TOPK ? ncand : TOPK;

    // ---- P4: IoU suppression masks. Row i split: main thread (tid=i) does the
    //      low half of its word span, helper (tid=200+i, i<184) the high half.
    {
        int i = -1, w0 = 0, w1 = 0;
        if (tid < TOPK) {
            i = tid;
            int wl = i >> 5, span = NW - wl;
            int mine = (i < 184) ? ((span + 1) >> 1) : span;
            w0 = wl; w1 = wl + mine;
        } else if (tid - TOPK < 184) {
            i = tid - TOPK;
            int wl = i >> 5, span = NW - wl;
            w0 = wl + ((span + 1) >> 1); w1 = NW;
        }
        if (i >= 0 && i < nval) {
            if (tid < TOPK)
                for (int w = 0; w < (i >> 5); w++) sup[i * SUPW + w] = 0u;
            float4 A = sbx[i];
            float aa = sar[i];
            for (int w = w0; w < w1; w++) {
                int j0 = w * 32;
                uint32_t m = 0;
#pragma unroll
                for (int jj = 0; jj < 32; jj++) {
                    int j = j0 + jj;
                    float4 B = sbx[j];
                    float xx1 = fmaxf(A.x, B.x);
                    float yy1 = fmaxf(A.y, B.y);
                    float xx2 = fminf(A.z, B.z);
                    float yy2 = fminf(A.w, B.w);
                    float iw = fmaxf(xx2 - xx1, 0.0f);
                    float ih = fmaxf(yy2 - yy1, 0.0f);
                    float inter = iw * ih;
                    float uni = aa + sar[j] - inter;
                    uint32_t bit = 0;
                    if (inter > uni * NMS_HI) bit = 1u << jj;
                    else if (inter > uni * NMS_LO) {
                        if (inter / fmaxf(uni, 1e-12f) > NMS_T) bit = 1u << jj;  // exact ref
                    }
                    m |= bit;
                }
                uint32_t um = (nval >= j0 + 32) ? 0xFFFFFFFFu
                             : ((nval > j0) ? ((1u << (nval - j0)) - 1u) : 0u);
                if (w == (i >> 5))
                    um = (i - j0 < 31) ? (um & (0xFFFFFFFFu << (i - j0 + 1))) : 0u;
                sup[i * SUPW + w] = m & um;
            }
        }
    }
    __syncthreads();

    // ---- P5: warp-parallel NMS sweep (warp 0) + popc compaction bases ----
    if (tid < 32) {
        uint32_t alive_w = 0xFFFFFFFFu;
        int nchunks = (nval + 31) >> 5;
        for (int g = 0; g < nchunks; g++) {
            int rem = nval - g * 32;
            uint32_t vm = (rem >= 32) ? 0xFFFFFFFFu : ((1u << rem) - 1u);
            uint32_t ag = __shfl_sync(0xFFFFFFFFu, alive_w, g) & vm;
            // intra-chunk serial resolve via shuffles (register chain, no LDS)
            uint32_t selfm = (lane < rem) ? sup[(g * 32 + lane) * SUPW + g] : 0u;
#pragma unroll
            for (int bit = 0; bit < 32; bit++) {
                uint32_t sm = __shfl_sync(0xFFFFFFFFu, selfm, bit);
                if ((ag >> bit) & 1u) ag &= ~sm;
            }
            if (lane == g) alive_w = ag;
            // apply chunk g's alive rows to later words (independent LDS, pipelined)
            uint32_t acc = 0;
            int waddr = (lane < NW) ? lane : NW - 1;
#pragma unroll
            for (int bit = 0; bit < 32; bit++) {
                uint32_t s = (bit < rem) ? sup[(g * 32 + bit) * SUPW + waddr] : 0u;
                if ((ag >> bit) & 1u) acc |= s;
            }
            if (lane > g && lane < NW) alive_w &= ~acc;
        }
        uint32_t aw = (lane < NW && lane < nchunks) ? alive_w : 0u;
        if (lane == nchunks - 1) {
            int rem = nval - lane * 32;
            if (rem < 32) aw &= ((1u << (rem > 0 ? rem : 0)) - 1u);
        }
        int pc = __popc(aw);
        int pre = pc;
#pragma unroll
        for (int d = 1; d < 32; d <<= 1) {
            int o = __shfl_up_sync(0xFFFFFFFFu, pre, d);
            if (lane >= d) pre += o;
        }
        if (lane < NW) { salive[lane] = aw; sbase[lane] = pre - pc; }
    }
    __syncthreads();

    // ---- P6: write kept rows compacted to front ----
    for (int i = tid; i < nval; i += NTB) {
        int w = i >> 5, bit = i & 31;
        uint32_t aw = salive[w];
        if ((aw >> bit) & 1u) {
            int q = sbase[w] + __popc(aw & ((1u << bit) - 1u));
            float* r = orow + q * 5;
            float4 bx = sbx[i];
            r[0] = ssc[i];
            r[1] = bx.x;
            r[2] = bx.y;
            r[3] = bx.z;
            r[4] = bx.w;
        }
    }
}

// ---------------------------------------------------------------------------
// Streams/events for pipelined chunks, created once at module load (no device
// memory allocation; no per-call state in kernel_launch).
// ---------------------------------------------------------------------------
static cudaStream_t g_s[NCHUNK];
static cudaEvent_t g_evA[NCHUNK], g_evB[NCHUNK], g_e0;
static struct PipeInit {
    PipeInit() {
        for (int i = 0; i < NCHUNK; i++) {
            cudaStreamCreateWithFlags(&g_s[i], cudaStreamNonBlocking);
            cudaEventCreateWithFlags(&g_evA[i], cudaEventDisableTiming);
            cudaEventCreateWithFlags(&g_evB[i], cudaEventDisableTiming);
        }
        cudaEventCreateWithFlags(&g_e0, cudaEventDisableTiming);
    }
} g_pipe_init;

extern "C" void kernel_launch(void* const* d_in, const int* in_sizes, int n_in,
                              void* d_out, int out_size)
{
    const float* loc    = (const float*)d_in[0];
    const float* conf   = (const float*)d_in[1];
    const float* priors = (const float*)d_in[2];
    float* out = (float*)d_out;

    cudaEventRecord(g_e0, 0);
    for (int ch = 0; ch < NCHUNK; ch++) {
        cudaStreamWaitEvent(g_s[ch], g_e0, 0);
        if (ch > 0) cudaStreamWaitEvent(g_s[ch], g_evA[ch - 1], 0);  // chain A's
        ssd_decode_softmax<<<(IMGS * NPRI + 255) / 256, 256, 0, g_s[ch]>>>(
            loc, conf, priors, ch * IMGS);
        cudaEventRecord(g_evA[ch], g_s[ch]);
        ssd_select_nms<<<IMGS * NCLS, NTB, 0, g_s[ch]>>>(out, ch * IMGS);
        cudaEventRecord(g_evB[ch], g_s[ch]);
        cudaStreamWaitEvent(0, g_evB[ch], 0);                        // join
    }
}

// round 8
// speedup vs baseline: 1.0331x; 1.0331x over previous
#include <cuda_runtime.h>
#include <cstdint>

// ---------------------------------------------------------------------------
// SSD post-processing:
//   inputs:  loc [32,8732,4] f32, conf [32,8732,21] f32, priors [8732,4] f32
//   output:  [32,21,200,5] f32  rows = [score, x1, y1, x2, y2]
// ---------------------------------------------------------------------------

#define BATCH 32
#define NPRI  8732
#define NPRI4 2183          /* 8732 / 4 exactly */
#define NCLS  21
#define TOPK  200
#define CAP   256           /* candidate capacity (common path) */
#define NW    7             /* ceil(200/32) suppression words */
#define SUPW  8             /* padded row width */
#define NTB   384           /* threads per select block */
#define CITER 6             /* ceil(NPRI4 / NTB) */
#define CONF_T 0.01f
#define NMS_T  0.45f
#define NMS_HI 0.45000180f  /* 0.45*(1+4e-6) */
#define NMS_LO 0.44999820f  /* 0.45*(1-4e-6) */
#define BASE16 0x3C00u      /* top16 of float bits; all valid keys above this */

// scratch (module-load allocated, not runtime alloc)
__device__ __align__(16) uint32_t g_keys[BATCH][NCLS-1][NPRI];
__device__ float4 g_boxes[BATCH][NPRI];

// ---------------------------------------------------------------------------
// Kernel A: softmax + decode. One thread per (b, prior). HBM/issue bound.
// ---------------------------------------------------------------------------
__global__ __launch_bounds__(256) void ssd_decode_softmax(
    const float* __restrict__ loc,
    const float* __restrict__ conf,
    const float* __restrict__ priors)
{
    int t = blockIdx.x * blockDim.x + threadIdx.x;
    if (t >= BATCH * NPRI) return;
    int b = t / NPRI;
    int p = t - b * NPRI;

    const float* cf = conf + (size_t)t * NCLS;
    float v[NCLS];
    float m = -1e30f;
#pragma unroll
    for (int c = 0; c < NCLS; c++) {
        float x = cf[c];
        x = fminf(fmaxf(x, -100.0f), 100.0f);
        v[c] = x;
        m = fmaxf(m, x);
    }
    float s = 0.0f;
#pragma unroll
    for (int c = 0; c < NCLS; c++) { v[c] = expf(v[c] - m); s += v[c]; }

    const float4 lp4 = ((const float4*)loc)[t];
    const float4 pr4 = ((const float4*)priors)[p];
    float p0 = fmaxf(pr4.x, 1e-6f);
    float p1 = fmaxf(pr4.y, 1e-6f);
    float p2 = fmaxf(pr4.z, 1e-6f);
    float p3 = fmaxf(pr4.w, 1e-6f);
    float cx = p0 + lp4.x * 0.1f * p2;
    float cy = p1 + lp4.y * 0.1f * p3;
    float lw = fminf(fmaxf(lp4.z * 0.2f, -4.0f), 4.0f);
    float lh = fminf(fmaxf(lp4.w * 0.2f, -4.0f), 4.0f);
    float w = p2 * expf(lw);
    float h = p3 * expf(lh);
    float x1 = fminf(fmaxf(cx - w / 2.0f, 0.0f), 1.0f);
    float y1 = fminf(fmaxf(cy - h / 2.0f, 0.0f), 1.0f);
    float x2 = fminf(fmaxf(cx + w / 2.0f, 0.0f), 1.0f);
    float y2 = fminf(fmaxf(cy + h / 2.0f, 0.0f), 1.0f);
    g_boxes[b][p] = make_float4(x1, y1, x2, y2);

    bool bvalid = (x2 > x1 + 1e-6f) && (y2 > y1 + 1e-6f);
#pragma unroll
    for (int c = 1; c < NCLS; c++) {
        float sc = v[c] / s;
        uint32_t key = (bvalid && sc > CONF_T) ? __float_as_uint(sc) : 0u;
        g_keys[b][c - 1][p] = key;
    }
}

// ---------------------------------------------------------------------------
// Kernel B: per (image,class): x4-replicated smem histogram select,
// warp-aggregated collect, O(n^2) exact rank, split-row IoU masks,
// warp-parallel sweep. 384 threads, 5 blocks/SM -> single wave (672 blocks).
// ---------------------------------------------------------------------------
__global__ __launch_bounds__(NTB, 5) void ssd_select_nms(float* __restrict__ out)
{
    __shared__ int hist[4][1024];      /* x4 replicated to cut ATOMS conflicts */
    __shared__ int part[256];
    __shared__ unsigned long long spk[CAP];
    __shared__ uint32_t sup[TOPK * SUPW];
    __shared__ float4 sbx[224];        /* padded: IoU reads j up to 223 (masked) */
    __shared__ float sar[224], ssc[TOPK];
    __shared__ uint32_t salive[8];
    __shared__ int sbase[8];
    __shared__ int sh[8];

    int bc = blockIdx.x;
    int b = bc / NCLS;
    int c = bc - b * NCLS;
    int tid = threadIdx.x;
    int lane = tid & 31;
    int* h0 = hist[0];
    float* orow = out + (size_t)bc * (TOPK * 5);

    if (c == 0) {
        for (int i = tid; i < TOPK * 5; i += NTB) orow[i] = 0.0f;
        return;
    }

    const uint32_t* gk = &g_keys[b][c - 1][0];
    const uint4* gk4 = (const uint4*)gk;

    // ---- P0: 16-bit digit histogram, 4 replicas (warp%4), then merge ----
    for (int i = tid; i < 4096; i += NTB) ((int*)hist)[i] = 0;
    __syncthreads();
    {
        int* hw = hist[(tid >> 5) & 3];
        for (int i = tid; i < NPRI4; i += NTB) {
            uint4 v = gk4[i];
            if (v.x) atomicAdd(&hw[(v.x >> 16) - BASE16], 1);
            if (v.y) atomicAdd(&hw[(v.y >> 16) - BASE16], 1);
            if (v.z) atomicAdd(&hw[(v.z >> 16) - BASE16], 1);
            if (v.w) atomicAdd(&hw[(v.w >> 16) - BASE16], 1);
        }
    }
    __syncthreads();
    if (tid < 256) {
        int4 a0 = ((const int4*)hist[0])[tid];
        int4 a1 = ((const int4*)hist[1])[tid];
        int4 a2 = ((const int4*)hist[2])[tid];
        int4 a3 = ((const int4*)hist[3])[tid];
        int4 s4 = make_int4(a0.x + a1.x + a2.x + a3.x,
                            a0.y + a1.y + a2.y + a3.y,
                            a0.z + a1.z + a2.z + a3.z,
                            a0.w + a1.w + a2.w + a3.w);
        ((int4*)hist[0])[tid] = s4;
        part[tid] = s4.x + s4.y + s4.z + s4.w;
    }
    __syncthreads();

    // ---- P1: warp 0 locates the 200th-largest digit via suffix scan ----
    if (tid < 32) {
        int s = 0;
#pragma unroll
        for (int q = 0; q < 8; q++) s += part[tid * 8 + q];
        int suf = s;
#pragma unroll
        for (int d = 1; d < 32; d <<= 1) {
            int o = __shfl_down_sync(0xFFFFFFFFu, suf, d);
            if (tid + d < 32) suf += o;
        }
        int sufN = __shfl_down_sync(0xFFFFFFFFu, suf, 1);
        if (tid == 31) sufN = 0;
        if (tid == 0) { sh[0] = -1; sh[6] = 0; }
        __syncwarp();
        if (suf >= TOPK && sufN < TOPK) { sh[0] = tid; sh[1] = sufN; }
        __syncwarp();
        if (tid == 0 && sh[0] >= 0) {
            int cum = sh[1];
            int d = sh[0] * 32 + 31;
            for (;; d--) { cum += h0[d]; if (cum >= TOPK) break; }
            sh[3] = d;                // digit of 200th value
            sh[4] = cum - h0[d];      // count with digit > d
            sh[5] = h0[d];
        }
    }
    __syncthreads();

    int ncand;
    bool rare = (sh[0] >= 0) && (sh[4] + sh[5] > CAP);
    if (!rare) {
        // ---- P2 common: collect keys >= digit floor, warp-aggregated push ----
        uint32_t thrK = (sh[0] < 0) ? (BASE16 << 16)
                                    : ((uint32_t)(BASE16 + (uint32_t)sh[3]) << 16);
        for (int i = tid; i < TOPK; i += NTB) ssc[i] = -1.0f;
#pragma unroll
        for (int it = 0; it < CITER; it++) {
            int i = tid + it * NTB;
            uint4 v = (i < NPRI4) ? gk4[i] : make_uint4(0u, 0u, 0u, 0u);
            int base4 = i * 4;
#pragma unroll
            for (int comp = 0; comp < 4; comp++) {
                uint32_t k = (comp == 0) ? v.x : (comp == 1) ? v.y : (comp == 2) ? v.z : v.w;
                int take = (k >= thrK);
                uint32_t bm = __ballot_sync(0xFFFFFFFFu, take);
                if (bm) {
                    int ldr = __ffs(bm) - 1;
                    int pos = 0;
                    if (lane == ldr) pos = atomicAdd(&sh[6], __popc(bm));
                    pos = __shfl_sync(0xFFFFFFFFu, pos, ldr);
                    if (take) {
                        int off = __popc(bm & ((1u << lane) - 1u));
                        spk[pos + off] = ((unsigned long long)k << 32)
                                       | (uint32_t)~(uint32_t)(base4 + comp);
                    }
                }
            }
        }
        __syncthreads();
        ncand = sh[6];
    } else {
        // ---- P2 rare (massive ties at cut digit): exact 32-bit refine ----
        for (int i = tid; i < TOPK; i += NTB) ssc[i] = -1.0f;
        uint32_t top16 = BASE16 + (uint32_t)sh[3];
        int cnt_gt = sh[4];
        if (tid < 256) h0[tid] = 0;
        __syncthreads();
        for (int i = tid; i < NPRI; i += NTB) {
            uint32_t k = gk[i];
            if ((k >> 16) == top16) atomicAdd(&h0[(k >> 8) & 0xFF], 1);
        }
        __syncthreads();
        if (tid == 0) {
            int cum = cnt_gt; int d = 255;
            for (;; d--) { cum += h0[d]; if (cum >= TOPK) break; }
            sh[3] = d; sh[4] = cum - h0[d];
        }
        __syncthreads();
        uint32_t pre24 = (top16 << 8) | (uint32_t)sh[3];
        cnt_gt = sh[4];
        if (tid < 256) h0[tid] = 0;
        __syncthreads();
        for (int i = tid; i < NPRI; i += NTB) {
            uint32_t k = gk[i];
            if ((k >> 8) == pre24) atomicAdd(&h0[k & 0xFF], 1);
        }
        __syncthreads();
        if (tid == 0) {
            int cum = cnt_gt; int d = 255;
            for (;; d--) { cum += h0[d]; if (cum >= TOPK) break; }
            sh[3] = d;
        }
        __syncthreads();
        uint32_t thr = (pre24 << 8) | (uint32_t)sh[3];
        for (int i = tid; i < NPRI; i += NTB) {
            uint32_t k = gk[i];
            if (k > thr) { int p = atomicAdd(&sh[6], 1); spk[p] = ((unsigned long long)k << 32) | (uint32_t)~(uint32_t)i; }
        }
        __syncthreads();
        if (tid == 0) {   // append ties in ascending index order
            int p = sh[6];
            for (int i = 0; i < NPRI && p < TOPK; i++)
                if (gk[i] == thr) { spk[p++] = ((unsigned long long)thr << 32) | (uint32_t)~(uint32_t)i; }
            sh[6] = p;
        }
        __syncthreads();
        ncand = sh[6];
    }

    // ---- P3: exact rank (key desc, index asc) + gather; idle threads zero out ----
    if (tid < ncand) {
        unsigned long long mypk = spk[tid];
        int rank = 0;
#pragma unroll 4
        for (int j = 0; j < ncand; j++) rank += (spk[j] > mypk) ? 1 : 0;
        if (rank < TOPK) {
            uint32_t kk = (uint32_t)(mypk >> 32);
            uint32_t idx = ~(uint32_t)mypk;
            float4 bx = g_boxes[b][idx];
            ssc[rank] = __uint_as_float(kk);
            sbx[rank] = bx;
            sar[rank] = (bx.z - bx.x) * (bx.w - bx.y);
        }
    } else if (tid >= 256) {
        for (int i = tid - 256; i < TOPK * 5; i += NTB - 256) orow[i] = 0.0f;
    }
    __syncthreads();
    int nval = ncand < TOPK ? ncand : TOPK;

    // ---- P4: IoU suppression masks. Row i split: main thread (tid=i) does the
    //      low half of its word span, helper (tid=200+i, i<184) the high half.
    {
        int i = -1, w0 = 0, w1 = 0;
        if (tid < TOPK) {
            i = tid;
            int wl = i >> 5, span = NW - wl;
            int mine = (i < 184) ? ((span + 1) >> 1) : span;
            w0 = wl; w1 = wl + mine;
        } else if (tid - TOPK < 184) {
            i = tid - TOPK;
            int wl = i >> 5, span = NW - wl;
            w0 = wl + ((span + 1) >> 1); w1 = NW;
        }
        if (i >= 0 && i < nval) {
            if (tid < TOPK)
                for (int w = 0; w < (i >> 5); w++) sup[i * SUPW + w] = 0u;
            float4 A = sbx[i];
            float aa = sar[i];
            for (int w = w0; w < w1; w++) {
                int j0 = w * 32;
                uint32_t m = 0;
#pragma unroll
                for (int jj = 0; jj < 32; jj++) {
                    int j = j0 + jj;
                    float4 B = sbx[j];
                    float xx1 = fmaxf(A.x, B.x);
                    float yy1 = fmaxf(A.y, B.y);
                    float xx2 = fminf(A.z, B.z);
                    float yy2 = fminf(A.w, B.w);
                    float iw = fmaxf(xx2 - xx1, 0.0f);
                    float ih = fmaxf(yy2 - yy1, 0.0f);
                    float inter = iw * ih;
                    float uni = aa + sar[j] - inter;
                    uint32_t bit = 0;
                    if (inter > uni * NMS_HI) bit = 1u << jj;
                    else if (inter > uni * NMS_LO) {
                        if (inter / fmaxf(uni, 1e-12f) > NMS_T) bit = 1u << jj;  // exact ref
                    }
                    m |= bit;
                }
                uint32_t um = (nval >= j0 + 32) ? 0xFFFFFFFFu
                             : ((nval > j0) ? ((1u << (nval - j0)) - 1u) : 0u);
                if (w == (i >> 5))
                    um = (i - j0 < 31) ? (um & (0xFFFFFFFFu << (i - j0 + 1))) : 0u;
                sup[i * SUPW + w] = m & um;
            }
        }
    }
    __syncthreads();

    // ---- P5: warp-parallel NMS sweep (warp 0) + popc compaction bases ----
    if (tid < 32) {
        uint32_t alive_w = 0xFFFFFFFFu;
        int nchunks = (nval + 31) >> 5;
        for (int g = 0; g < nchunks; g++) {
            int rem = nval - g * 32;
            uint32_t vm = (rem >= 32) ? 0xFFFFFFFFu : ((1u << rem) - 1u);
            uint32_t ag = __shfl_sync(0xFFFFFFFFu, alive_w, g) & vm;
            // intra-chunk serial resolve via shuffles (register chain, no LDS)
            uint32_t selfm = (lane < rem) ? sup[(g * 32 + lane) * SUPW + g] : 0u;
#pragma unroll
            for (int bit = 0; bit < 32; bit++) {
                uint32_t sm = __shfl_sync(0xFFFFFFFFu, selfm, bit);
                if ((ag >> bit) & 1u) ag &= ~sm;
            }
            if (lane == g) alive_w = ag;
            // apply chunk g's alive rows to later words (independent LDS, pipelined)
            uint32_t acc = 0;
            int waddr = (lane < NW) ? lane : NW - 1;
#pragma unroll
            for (int bit = 0; bit < 32; bit++) {
                uint32_t s = (bit < rem) ? sup[(g * 32 + bit) * SUPW + waddr] : 0u;
                if ((ag >> bit) & 1u) acc |= s;
            }
            if (lane > g && lane < NW) alive_w &= ~acc;
        }
        uint32_t aw = (lane < NW && lane < nchunks) ? alive_w : 0u;
        if (lane == nchunks - 1) {
            int rem = nval - lane * 32;
            if (rem < 32) aw &= ((1u << (rem > 0 ? rem : 0)) - 1u);
        }
        int pc = __popc(aw);
        int pre = pc;
#pragma unroll
        for (int d = 1; d < 32; d <<= 1) {
            int o = __shfl_up_sync(0xFFFFFFFFu, pre, d);
            if (lane >= d) pre += o;
        }
        if (lane < NW) { salive[lane] = aw; sbase[lane] = pre - pc; }
    }
    __syncthreads();

    // ---- P6: write kept rows compacted to front ----
    for (int i = tid; i < nval; i += NTB) {
        int w = i >> 5, bit = i & 31;
        uint32_t aw = salive[w];
        if ((aw >> bit) & 1u) {
            int q = sbase[w] + __popc(aw & ((1u << bit) - 1u));
            float* r = orow + q * 5;
            float4 bx = sbx[i];
            r[0] = ssc[i];
            r[1] = bx.x;
            r[2] = bx.y;
            r[3] = bx.z;
            r[4] = bx.w;
        }
    }
}

// ---------------------------------------------------------------------------
extern "C" void kernel_launch(void* const* d_in, const int* in_sizes, int n_in,
                              void* d_out, int out_size)
{
    const float* loc    = (const float*)d_in[0];
    const float* conf   = (const float*)d_in[1];
    const float* priors = (const float*)d_in[2];
    float* out = (float*)d_out;

    ssd_decode_softmax<<<(BATCH * NPRI + 255) / 256, 256>>>(loc, conf, priors);
    ssd_select_nms<<<BATCH * NCLS, NTB>>>(out);
}

// round 9
// speedup vs baseline: 1.0858x; 1.0510x over previous
#include <cuda_runtime.h>
#include <cstdint>

// ---------------------------------------------------------------------------
// SSD post-processing:
//   inputs:  loc [32,8732,4] f32, conf [32,8732,21] f32, priors [8732,4] f32
//   output:  [32,21,200,5] f32  rows = [score, x1, y1, x2, y2]
// ---------------------------------------------------------------------------

#define BATCH 32
#define NPRI  8732
#define NPRI4 2183          /* 8732 / 4 exactly */
#define NCLS  21
#define TOPK  200
#define CAP   256           /* candidate capacity (common path) */
#define NW    7             /* ceil(200/32) suppression words */
#define SUPW  8             /* padded row width */
#define NTB   384           /* threads per select block */
#define CITER 6             /* ceil(NPRI4 / NTB) */
#define NTASK 872           /* upper-triangle (row,word) tasks */
#define J0    160           /* rank split point: main j<J0, helper j>=J0 */
#define CONF_T 0.01f
#define NMS_T  0.45f
#define NMS_HI 0.45000180f  /* 0.45*(1+4e-6) */
#define NMS_LO 0.44999820f  /* 0.45*(1-4e-6) */
#define BASE16 0x3C00u      /* top16 of float bits; all valid keys above this */

// scratch (module-load allocated, not runtime alloc)
__device__ __align__(16) uint32_t g_keys[BATCH][NCLS-1][NPRI];
__device__ float4 g_boxes[BATCH][NPRI];

// ---------------------------------------------------------------------------
// Kernel A: softmax + decode. One thread per (b, prior). HBM-roofline bound.
// ---------------------------------------------------------------------------
__global__ __launch_bounds__(256) void ssd_decode_softmax(
    const float* __restrict__ loc,
    const float* __restrict__ conf,
    const float* __restrict__ priors)
{
    int t = blockIdx.x * blockDim.x + threadIdx.x;
    if (t >= BATCH * NPRI) return;
    int b = t / NPRI;
    int p = t - b * NPRI;

    const float* cf = conf + (size_t)t * NCLS;
    float v[NCLS];
    float m = -1e30f;
#pragma unroll
    for (int c = 0; c < NCLS; c++) {
        float x = cf[c];
        x = fminf(fmaxf(x, -100.0f), 100.0f);
        v[c] = x;
        m = fmaxf(m, x);
    }
    float s = 0.0f;
#pragma unroll
    for (int c = 0; c < NCLS; c++) { v[c] = expf(v[c] - m); s += v[c]; }

    const float4 lp4 = ((const float4*)loc)[t];
    const float4 pr4 = ((const float4*)priors)[p];
    float p0 = fmaxf(pr4.x, 1e-6f);
    float p1 = fmaxf(pr4.y, 1e-6f);
    float p2 = fmaxf(pr4.z, 1e-6f);
    float p3 = fmaxf(pr4.w, 1e-6f);
    float cx = p0 + lp4.x * 0.1f * p2;
    float cy = p1 + lp4.y * 0.1f * p3;
    float lw = fminf(fmaxf(lp4.z * 0.2f, -4.0f), 4.0f);
    float lh = fminf(fmaxf(lp4.w * 0.2f, -4.0f), 4.0f);
    float w = p2 * expf(lw);
    float h = p3 * expf(lh);
    float x1 = fminf(fmaxf(cx - w / 2.0f, 0.0f), 1.0f);
    float y1 = fminf(fmaxf(cy - h / 2.0f, 0.0f), 1.0f);
    float x2 = fminf(fmaxf(cx + w / 2.0f, 0.0f), 1.0f);
    float y2 = fminf(fmaxf(cy + h / 2.0f, 0.0f), 1.0f);
    g_boxes[b][p] = make_float4(x1, y1, x2, y2);

    bool bvalid = (x2 > x1 + 1e-6f) && (y2 > y1 + 1e-6f);
#pragma unroll
    for (int c = 1; c < NCLS; c++) {
        float sc = v[c] / s;
        uint32_t key = (bvalid && sc > CONF_T) ? __float_as_uint(sc) : 0u;
        g_keys[b][c - 1][p] = key;
    }
}

// ---------------------------------------------------------------------------
// Kernel B: per (image,class): smem histogram select, warp-aggregated collect,
// split O(n^2) rank, task-table IoU masks, warp-parallel sweep + compaction.
// 384 threads, 5 blocks/SM -> single wave for 672 blocks. smem kept small
// (~20KB) to preserve L1 carveout for the two key scans.
// ---------------------------------------------------------------------------
__global__ __launch_bounds__(NTB, 5) void ssd_select_nms(float* __restrict__ out)
{
    __shared__ int hist[1024];
    __shared__ int part[256];
    __shared__ unsigned long long spk[CAP];
    __shared__ uint32_t sup[TOPK * SUPW];
    __shared__ float4 sbx[224];        /* padded: IoU reads j up to 223 (masked) */
    __shared__ float sar[224], ssc[TOPK];
    __shared__ int prank[256];
    __shared__ uint32_t salive[8];
    __shared__ int sbase[8];
    __shared__ int sh[8];

    int bc = blockIdx.x;
    int b = bc / NCLS;
    int c = bc - b * NCLS;
    int tid = threadIdx.x;
    int lane = tid & 31;
    float* orow = out + (size_t)bc * (TOPK * 5);

    if (c == 0) {
        for (int i = tid; i < TOPK * 5; i += NTB) orow[i] = 0.0f;
        return;
    }

    const uint32_t* gk = &g_keys[b][c - 1][0];
    const uint4* gk4 = (const uint4*)gk;

    // ---- P0: 16-bit digit histogram in smem (skip zero keys) ----
    for (int i = tid; i < 1024; i += NTB) hist[i] = 0;
    __syncthreads();
    for (int i = tid; i < NPRI4; i += NTB) {
        uint4 v = gk4[i];
        if (v.x) atomicAdd(&hist[(v.x >> 16) - BASE16], 1);
        if (v.y) atomicAdd(&hist[(v.y >> 16) - BASE16], 1);
        if (v.z) atomicAdd(&hist[(v.z >> 16) - BASE16], 1);
        if (v.w) atomicAdd(&hist[(v.w >> 16) - BASE16], 1);
    }
    __syncthreads();
    if (tid < 256) {
        int4 h4 = ((const int4*)hist)[tid];
        part[tid] = h4.x + h4.y + h4.z + h4.w;
    }
    __syncthreads();

    // ---- P1: warp 0 locates the 200th-largest digit via suffix scan ----
    if (tid < 32) {
        int s = 0;
#pragma unroll
        for (int q = 0; q < 8; q++) s += part[tid * 8 + q];
        int suf = s;
#pragma unroll
        for (int d = 1; d < 32; d <<= 1) {
            int o = __shfl_down_sync(0xFFFFFFFFu, suf, d);
            if (tid + d < 32) suf += o;
        }
        int sufN = __shfl_down_sync(0xFFFFFFFFu, suf, 1);
        if (tid == 31) sufN = 0;
        if (tid == 0) { sh[0] = -1; sh[6] = 0; }
        __syncwarp();
        if (suf >= TOPK && sufN < TOPK) { sh[0] = tid; sh[1] = sufN; }
        __syncwarp();
        if (tid == 0 && sh[0] >= 0) {
            int cum = sh[1];
            int d = sh[0] * 32 + 31;
            for (;; d--) { cum += hist[d]; if (cum >= TOPK) break; }
            sh[3] = d;                // digit of 200th value
            sh[4] = cum - hist[d];    // count with digit > d
            sh[5] = hist[d];
        }
    }
    __syncthreads();

    int ncand;
    bool rare = (sh[0] >= 0) && (sh[4] + sh[5] > CAP);
    if (!rare) {
        // ---- P2 common: collect keys >= digit floor, warp-aggregated push ----
        uint32_t thrK = (sh[0] < 0) ? (BASE16 << 16)
                                    : ((uint32_t)(BASE16 + (uint32_t)sh[3]) << 16);
        for (int i = tid; i < TOPK; i += NTB) ssc[i] = -1.0f;
#pragma unroll
        for (int it = 0; it < CITER; it++) {
            int i = tid + it * NTB;
            uint4 v = (i < NPRI4) ? gk4[i] : make_uint4(0u, 0u, 0u, 0u);
            int base4 = i * 4;
#pragma unroll
            for (int comp = 0; comp < 4; comp++) {
                uint32_t k = (comp == 0) ? v.x : (comp == 1) ? v.y : (comp == 2) ? v.z : v.w;
                int take = (k >= thrK);
                uint32_t bm = __ballot_sync(0xFFFFFFFFu, take);
                if (bm) {
                    int ldr = __ffs(bm) - 1;
                    int pos = 0;
                    if (lane == ldr) pos = atomicAdd(&sh[6], __popc(bm));
                    pos = __shfl_sync(0xFFFFFFFFu, pos, ldr);
                    if (take) {
                        int off = __popc(bm & ((1u << lane) - 1u));
                        spk[pos + off] = ((unsigned long long)k << 32)
                                       | (uint32_t)~(uint32_t)(base4 + comp);
                    }
                }
            }
        }
        __syncthreads();
        ncand = sh[6];
    } else {
        // ---- P2 rare (massive ties at cut digit): exact 32-bit refine ----
        for (int i = tid; i < TOPK; i += NTB) ssc[i] = -1.0f;
        uint32_t top16 = BASE16 + (uint32_t)sh[3];
        int cnt_gt = sh[4];
        if (tid < 256) hist[tid] = 0;
        __syncthreads();
        for (int i = tid; i < NPRI; i += NTB) {
            uint32_t k = gk[i];
            if ((k >> 16) == top16) atomicAdd(&hist[(k >> 8) & 0xFF], 1);
        }
        __syncthreads();
        if (tid == 0) {
            int cum = cnt_gt; int d = 255;
            for (;; d--) { cum += hist[d]; if (cum >= TOPK) break; }
            sh[3] = d; sh[4] = cum - hist[d];
        }
        __syncthreads();
        uint32_t pre24 = (top16 << 8) | (uint32_t)sh[3];
        cnt_gt = sh[4];
        if (tid < 256) hist[tid] = 0;
        __syncthreads();
        for (int i = tid; i < NPRI; i += NTB) {
            uint32_t k = gk[i];
            if ((k >> 8) == pre24) atomicAdd(&hist[k & 0xFF], 1);
        }
        __syncthreads();
        if (tid == 0) {
            int cum = cnt_gt; int d = 255;
            for (;; d--) { cum += hist[d]; if (cum >= TOPK) break; }
            sh[3] = d;
        }
        __syncthreads();
        uint32_t thr = (pre24 << 8) | (uint32_t)sh[3];
        for (int i = tid; i < NPRI; i += NTB) {
            uint32_t k = gk[i];
            if (k > thr) { int p = atomicAdd(&sh[6], 1); spk[p] = ((unsigned long long)k << 32) | (uint32_t)~(uint32_t)i; }
        }
        __syncthreads();
        if (tid == 0) {   // append ties in ascending index order
            int p = sh[6];
            for (int i = 0; i < NPRI && p < TOPK; i++)
                if (gk[i] == thr) { spk[p++] = ((unsigned long long)thr << 32) | (uint32_t)~(uint32_t)i; }
            sh[6] = p;
        }
        __syncthreads();
        ncand = sh[6];
    }

    // ---- P3: exact rank (key desc, index asc), split main/helper.
    //      Main thread t (t < ncand) counts j in [0, J0);
    //      helper 256+h counts j in [J0, ncand) for candidates 2h, 2h+1.
    for (int i = tid; i < TOPK * 5; i += NTB) orow[i] = 0.0f;   // zero out rows
    if (tid < 256) prank[tid] = 0;
    __syncthreads();

    int rank_lo = 0;
    unsigned long long mypk = 0ull;
    if (tid < ncand) {
        mypk = spk[tid];
        int jend = (ncand < J0) ? ncand : J0;
#pragma unroll 4
        for (int j = 0; j < jend; j++) rank_lo += (spk[j] > mypk) ? 1 : 0;
    } else if (tid >= 256 && ncand > J0) {
        int c0 = (tid - 256) * 2, c1 = c0 + 1;
        if (c0 < ncand) {
            unsigned long long k0 = spk[c0];
            unsigned long long k1 = (c1 < ncand) ? spk[c1] : ~0ull;
            int r0 = 0, r1 = 0;
#pragma unroll 4
            for (int j = J0; j < ncand; j++) {
                unsigned long long kj = spk[j];
                r0 += (kj > k0) ? 1 : 0;
                r1 += (kj > k1) ? 1 : 0;
            }
            prank[c0] = r0;
            if (c1 < ncand) prank[c1] = r1;
        }
    }
    __syncthreads();
    if (tid < ncand) {
        int rank = rank_lo + prank[tid];
        if (rank < TOPK) {
            uint32_t kk = (uint32_t)(mypk >> 32);
            uint32_t idx = ~(uint32_t)mypk;
            float4 bx = g_boxes[b][idx];
            ssc[rank] = __uint_as_float(kk);
            sbx[rank] = bx;
            sar[rank] = (bx.z - bx.x) * (bx.w - bx.y);
        }
    }
    __syncthreads();
    int nval = ncand < TOPK ? ncand : TOPK;

    // ---- P4: IoU suppression masks, flat task table: 872 (row,word) tasks,
    //      <=3 per thread. Row low words zeroed by thread tid=row.
    if (tid < TOPK && tid < nval)
        for (int w = 0; w < (tid >> 5); w++) sup[tid * SUPW + w] = 0u;
#pragma unroll
    for (int rep = 0; rep < 3; rep++) {
        int t = tid + rep * NTB;
        if (t >= NTASK) break;
        int w, i;
        if (t < 192) {
            if (t < 32)       { w = 0; i = t; }
            else if (t < 96)  { w = 1; i = t - 32; }
            else              { w = 2; i = t - 96; }
        } else {
            if (t < 320)      { w = 3; i = t - 192; }
            else if (t < 480) { w = 4; i = t - 320; }
            else if (t < 672) { w = 5; i = t - 480; }
            else              { w = 6; i = t - 672; }
        }
        if (i >= nval) continue;
        float4 A = sbx[i];
        float aa = sar[i];
        int j0 = w * 32;
        uint32_t m = 0;
#pragma unroll
        for (int jj = 0; jj < 32; jj++) {
            int j = j0 + jj;
            float4 B = sbx[j];
            float xx1 = fmaxf(A.x, B.x);
            float yy1 = fmaxf(A.y, B.y);
            float xx2 = fminf(A.z, B.z);
            float yy2 = fminf(A.w, B.w);
            float iw = fmaxf(xx2 - xx1, 0.0f);
            float ih = fmaxf(yy2 - yy1, 0.0f);
            float inter = iw * ih;
            float uni = aa + sar[j] - inter;
            uint32_t bit = 0;
            if (inter > uni * NMS_HI) bit = 1u << jj;
            else if (inter > uni * NMS_LO) {
                if (inter / fmaxf(uni, 1e-12f) > NMS_T) bit = 1u << jj;  // exact ref
            }
            m |= bit;
        }
        uint32_t um = (nval >= j0 + 32) ? 0xFFFFFFFFu
                     : ((nval > j0) ? ((1u << (nval - j0)) - 1u) : 0u);
        if (w == (i >> 5))
            um = (i - j0 < 31) ? (um & (0xFFFFFFFFu << (i - j0 + 1))) : 0u;
        sup[i * SUPW + w] = m & um;
    }
    __syncthreads();

    // ---- P5: warp-parallel NMS sweep (warp 0) + popc compaction bases ----
    if (tid < 32) {
        uint32_t alive_w = 0xFFFFFFFFu;
        int nchunks = (nval + 31) >> 5;
        for (int g = 0; g < nchunks; g++) {
            int rem = nval - g * 32;
            uint32_t vm = (rem >= 32) ? 0xFFFFFFFFu : ((1u << rem) - 1u);
            uint32_t ag = __shfl_sync(0xFFFFFFFFu, alive_w, g) & vm;
            // intra-chunk serial resolve via shuffles (register chain, no LDS)
            uint32_t selfm = (lane < rem) ? sup[(g * 32 + lane) * SUPW + g] : 0u;
#pragma unroll
            for (int bit = 0; bit < 32; bit++) {
                uint32_t sm = __shfl_sync(0xFFFFFFFFu, selfm, bit);
                if ((ag >> bit) & 1u) ag &= ~sm;
            }
            if (lane == g) alive_w = ag;
            // apply chunk g's alive rows to later words (independent LDS, pipelined)
            uint32_t acc = 0;
            int waddr = (lane < NW) ? lane : NW - 1;
#pragma unroll
            for (int bit = 0; bit < 32; bit++) {
                uint32_t s = (bit < rem) ? sup[(g * 32 + bit) * SUPW + waddr] : 0u;
                if ((ag >> bit) & 1u) acc |= s;
            }
            if (lane > g && lane < NW) alive_w &= ~acc;
        }
        uint32_t aw = (lane < NW && lane < nchunks) ? alive_w : 0u;
        if (lane == nchunks - 1) {
            int rem = nval - lane * 32;
            if (rem < 32) aw &= ((1u << (rem > 0 ? rem : 0)) - 1u);
        }
        int pc = __popc(aw);
        int pre = pc;
#pragma unroll
        for (int d = 1; d < 32; d <<= 1) {
            int o = __shfl_up_sync(0xFFFFFFFFu, pre, d);
            if (lane >= d) pre += o;
        }
        if (lane < NW) { salive[lane] = aw; sbase[lane] = pre - pc; }
    }
    __syncthreads();

    // ---- P6: write kept rows compacted to front ----
    for (int i = tid; i < nval; i += NTB) {
        int w = i >> 5, bit = i & 31;
        uint32_t aw = salive[w];
        if ((aw >> bit) & 1u) {
            int q = sbase[w] + __popc(aw & ((1u << bit) - 1u));
            float* r = orow + q * 5;
            float4 bx = sbx[i];
            r[0] = ssc[i];
            r[1] = bx.x;
            r[2] = bx.y;
            r[3] = bx.z;
            r[4] = bx.w;
        }
    }
}

// ---------------------------------------------------------------------------
extern "C" void kernel_launch(void* const* d_in, const int* in_sizes, int n_in,
                              void* d_out, int out_size)
{
    const float* loc    = (const float*)d_in[0];
    const float* conf   = (const float*)d_in[1];
    const float* priors = (const float*)d_in[2];
    float* out = (float*)d_out;

    ssd_decode_softmax<<<(BATCH * NPRI + 255) / 256, 256>>>(loc, conf, priors);
    ssd_select_nms<<<BATCH * NCLS, NTB>>>(out);
}